// round 1
// baseline (speedup 1.0000x reference)
#include <cuda_runtime.h>

// ---- problem constants ----
#define LFULL (1 << 20)
#define L1    (1 << 19)
#define L2    (1 << 18)
#define L3    (1 << 17)
#define BATCH 64

// ---- tiling ----
#define T3 512                 // level-3 outputs per block
#define T1 (4 * T3)            // 2048 level-1 core outputs (hi1 written)
#define T2 (2 * T3)            // 1024 level-2 core outputs
#define N1 (T1 + 36)           // 2084 level-1 lo values incl. halo
#define N2 (T2 + 12)           // 1036 level-2 lo values incl. halo
#define NX (8 * T3 + 77)       // 4173 input samples incl. halo

// ---- flattened output offsets (tuple order: lo3, yh0, yh1, yh2) ----
#define OFF_YH0 8388608L       // 64 * L3
#define OFF_YH1 41943040L      // + 64 * L1
#define OFF_YH2 75497472L      // + 64 * 2 * L2

__global__ __launch_bounds__(256) void dtcwt1d_fused(
    const float* __restrict__ x,
    const float* __restrict__ h0o, const float* __restrict__ h1o,
    const float* __restrict__ h0a, const float* __restrict__ h1a,
    const float* __restrict__ h1b,
    float* __restrict__ out)
{
    __shared__ float sx[NX];
    __shared__ float s1[N1];
    __shared__ float s2[N2];
    __shared__ float f0o[5], f1o[7], f0a[14], f1a[14], f1b[14];

    const int tid = threadIdx.x;
    const int b   = blockIdx.y;
    const int M0  = blockIdx.x * T3;   // level-3 tile start
    const int N0  = 2 * M0;            // level-2 core start
    const int P0  = 4 * M0;            // level-1 core start
    const long X0 = 8L * M0;           // input tile start

    if (tid < 14) {
        f0a[tid] = h0a[tid];
        f1a[tid] = h1a[tid];
        f1b[tid] = h1b[tid];
        if (tid < 5) f0o[tid] = h0o[tid];
        if (tid < 7) f1o[tid] = h1o[tid];
    }

    // ---- load input tile + halo (zero outside sequence) ----
    const float* xb = x + (long)b * LFULL;
    for (int j = tid; j < NX; j += 256) {
        long g = X0 - 39 + j;
        sx[j] = (g >= 0 && g < LFULL) ? xb[g] : 0.f;
    }
    __syncthreads();

    // ---- level 1: lo1 -> smem (halo'd), hi1 -> gmem (core) ----
    // p = P0 - 18 + i ; lo window = x[2p-2 .. 2p+2] = sx[2i+1 .. 2i+5]
    //                    hi window = x[2p-3 .. 2p+3] = sx[2i   .. 2i+6]
    float* yh0 = out + OFF_YH0 + (long)b * L1;
    for (int i = tid; i < N1; i += 256) {
        const float v0 = sx[2*i],   v1 = sx[2*i+1], v2 = sx[2*i+2],
                    v3 = sx[2*i+3], v4 = sx[2*i+4], v5 = sx[2*i+5],
                    v6 = sx[2*i+6];
        const int p = P0 - 18 + i;
        float lo = f0o[0]*v1 + f0o[1]*v2 + f0o[2]*v3 + f0o[3]*v4 + f0o[4]*v5;
        s1[i] = (p >= 0 && p < L1) ? lo : 0.f;
        if (i >= 18 && i < 18 + T1) {
            float hi = f1o[0]*v0 + f1o[1]*v1 + f1o[2]*v2 + f1o[3]*v3
                     + f1o[4]*v4 + f1o[5]*v5 + f1o[6]*v6;
            yh0[p] = hi;
        }
    }
    __syncthreads();

    // ---- level 2: loa -> smem (halo'd), hia/hib -> gmem (core) ----
    // n = N0 - 6 + i ; window = lo1[2n-6 .. 2n+7] = s1[2i .. 2i+13]
    float* yh1 = out + OFF_YH1 + (long)b * (2L * L2);
    for (int i = tid; i < N2; i += 256) {
        float la = 0.f, ha = 0.f, hb = 0.f;
        #pragma unroll
        for (int t = 0; t < 14; ++t) {
            const float w = s1[2*i + t];
            la += f0a[t] * w;
            ha += f1a[t] * w;
            hb += f1b[t] * w;
        }
        const int n = N0 - 6 + i;
        s2[i] = (n >= 0 && n < L2) ? la : 0.f;
        if (i >= 6 && i < 6 + T2) {
            yh1[n]      = ha;
            yh1[L2 + n] = hb;
        }
    }
    __syncthreads();

    // ---- level 3: lo3, hia3, hib3 -> gmem ----
    // m = M0 + i ; window = lo2[2m-6 .. 2m+7] = s2[2i .. 2i+13]
    float* olo = out + (long)b * L3;
    float* yh2 = out + OFF_YH2 + (long)b * (2L * L3);
    for (int i = tid; i < T3; i += 256) {
        float la = 0.f, ha = 0.f, hb = 0.f;
        #pragma unroll
        for (int t = 0; t < 14; ++t) {
            const float w = s2[2*i + t];
            la += f0a[t] * w;
            ha += f1a[t] * w;
            hb += f1b[t] * w;
        }
        const int m = M0 + i;
        olo[m]      = la;
        yh2[m]      = ha;
        yh2[L3 + m] = hb;
    }
}

extern "C" void kernel_launch(void* const* d_in, const int* in_sizes, int n_in,
                              void* d_out, int out_size) {
    (void)in_sizes; (void)n_in; (void)out_size;
    // metadata order: x, h0o, h1o, h0a, h1a, h0b(unused), h1b
    dim3 grid(L3 / T3, BATCH);
    dtcwt1d_fused<<<grid, 256>>>(
        (const float*)d_in[0],
        (const float*)d_in[1], (const float*)d_in[2],
        (const float*)d_in[3], (const float*)d_in[4],
        (const float*)d_in[6],
        (float*)d_out);
}

// round 2
// speedup vs baseline: 3.3036x; 3.3036x over previous
#include <cuda_runtime.h>

// ---- problem constants ----
#define LFULL (1 << 20)
#define L1    (1 << 19)
#define L2    (1 << 18)
#define L3    (1 << 17)
#define BATCH 64

// ---- tiling (per block: T3 level-3 outputs of one batch row) ----
#define T3 512
#define T1 2048
#define T2 1024

// halo-padded local extents (all group-of-4 aligned)
#define NG1 524    // level-1 groups: lp = 4g+j in [0,2096), abs p = P0-24+lp
#define NG2 260    // level-2 groups: ln in [0,1040),        abs n = N0-8+ln
#define NG3 128    // level-3 groups: lm in [0,512),         abs m = M0+lm
#define NXQ 1050   // float4's of input tile (4200 floats), abs idx = X0-52+lx
#define NXH 2100   // per-plane x floats
#define NS1 1048   // s1 plane floats (2096/2)
#define NS2 520    // s2 plane floats (1040/2)

// ---- flattened output offsets (tuple order: lo3, yh0, yh1, yh2) ----
#define OFF_YH0 8388608L
#define OFF_YH1 41943040L
#define OFF_YH2 75497472L

__global__ __launch_bounds__(256) void dtcwt1d_fused(
    const float* __restrict__ x,
    const float* __restrict__ h0o, const float* __restrict__ h1o,
    const float* __restrict__ h0a,
    float* __restrict__ out)
{
    // even/odd deinterleaved planes -> unit-stride, conflict-free windows
    __shared__ __align__(16) float xe[NXH];
    __shared__ __align__(16) float xo[NXH];
    __shared__ __align__(16) float s1e[NS1];
    __shared__ __align__(16) float s1o[NS1];
    __shared__ __align__(16) float s2e[NS2];
    __shared__ __align__(16) float s2o[NS2];

    const int tid = threadIdx.x;
    const int b   = blockIdx.y;
    const int M0  = blockIdx.x * T3;
    const int N0  = 2 * M0;
    const int P0  = 4 * M0;
    const long X0 = 8L * M0;

    // ---- load + deinterleave input tile (zero outside [0, LFULL)) ----
    const float* xb = x + (long)b * LFULL;
    for (int j = tid; j < NXQ; j += 256) {
        long g0 = X0 - 52 + 4L * j;
        float4 v;
        if (g0 >= 0 && g0 + 3 < LFULL) {
            v = *(const float4*)(xb + g0);
        } else {
            v.x = (g0     >= 0 && g0     < LFULL) ? xb[g0]     : 0.f;
            v.y = (g0 + 1 >= 0 && g0 + 1 < LFULL) ? xb[g0 + 1] : 0.f;
            v.z = (g0 + 2 >= 0 && g0 + 2 < LFULL) ? xb[g0 + 2] : 0.f;
            v.w = (g0 + 3 >= 0 && g0 + 3 < LFULL) ? xb[g0 + 3] : 0.f;
        }
        *(float2*)(xe + 2 * j) = make_float2(v.x, v.z);
        *(float2*)(xo + 2 * j) = make_float2(v.y, v.w);
    }
    __syncthreads();

    // ---- level 1: lo1 -> planes, hi1 -> gmem (STG.128) ----
    // lo[p] = c0*xe[lp+1]+c2*xe[lp+2]+c4*xe[lp+3]+c1*xo[lp+1]+c3*xo[lp+2]
    // hi[p] = d0*xo[lp]+d2*xo[lp+1]+d4*xo[lp+2]+d6*xo[lp+3]
    //       + d1*xe[lp+1]+d3*xe[lp+2]+d5*xe[lp+3]
    {
        const float c0 = h0o[0], c1 = h0o[1], c2 = h0o[2], c3 = h0o[3], c4 = h0o[4];
        const float d0 = h1o[0], d1 = h1o[1], d2 = h1o[2], d3 = h1o[3],
                    d4 = h1o[4], d5 = h1o[5], d6 = h1o[6];
        float* yh0 = out + OFF_YH0 + (long)b * L1;
        for (int g = tid; g < NG1; g += 256) {
            const int lp0 = 4 * g;
            const float4 A0 = *(const float4*)(xe + lp0);
            const float4 A1 = *(const float4*)(xe + lp0 + 4);
            const float4 B0 = *(const float4*)(xo + lp0);
            const float4 B1 = *(const float4*)(xo + lp0 + 4);
            const float E[8] = {A0.x, A0.y, A0.z, A0.w, A1.x, A1.y, A1.z, A1.w};
            const float O[8] = {B0.x, B0.y, B0.z, B0.w, B1.x, B1.y, B1.z, B1.w};
            float lo[4], hi[4];
            #pragma unroll
            for (int j = 0; j < 4; ++j) {
                lo[j] = c0 * E[j + 1] + c2 * E[j + 2] + c4 * E[j + 3]
                      + c1 * O[j + 1] + c3 * O[j + 2];
                hi[j] = d0 * O[j] + d2 * O[j + 1] + d4 * O[j + 2] + d6 * O[j + 3]
                      + d1 * E[j + 1] + d3 * E[j + 2] + d5 * E[j + 3];
            }
            const int pb = P0 - 24 + lp0;
            #pragma unroll
            for (int j = 0; j < 4; ++j)
                if (pb + j < 0 || pb + j >= L1) lo[j] = 0.f;
            *(float2*)(s1e + 2 * g) = make_float2(lo[0], lo[2]);
            *(float2*)(s1o + 2 * g) = make_float2(lo[1], lo[3]);
            if (g >= 6 && g < 6 + T1 / 4)
                *(float4*)(yh0 + P0 + 4 * (g - 6)) =
                    make_float4(hi[0], hi[1], hi[2], hi[3]);
        }
    }
    __syncthreads();

    // ---- level 2: Q-shift. E=sum ae*we, O=sum ao*wo
    //   lo = E+O ; hb = O-E ; ha = sum ao[6-s]*we[s] - sum ae[6-s]*wo[s]
    {
        float ae[7], ao[7];
        #pragma unroll
        for (int s = 0; s < 7; ++s) { ae[s] = h0a[2 * s]; ao[s] = h0a[2 * s + 1]; }
        float* yh1 = out + OFF_YH1 + (long)b * (2L * L2);
        for (int g = tid; g < NG2; g += 256) {
            const int ln0 = 4 * g;
            const float4 A0 = *(const float4*)(s1e + ln0);
            const float4 A1 = *(const float4*)(s1e + ln0 + 4);
            const float4 A2 = *(const float4*)(s1e + ln0 + 8);
            const float4 B0 = *(const float4*)(s1o + ln0);
            const float4 B1 = *(const float4*)(s1o + ln0 + 4);
            const float4 B2 = *(const float4*)(s1o + ln0 + 8);
            const float we[12] = {A0.x, A0.y, A0.z, A0.w, A1.x, A1.y,
                                  A1.z, A1.w, A2.x, A2.y, A2.z, A2.w};
            const float wo[12] = {B0.x, B0.y, B0.z, B0.w, B1.x, B1.y,
                                  B1.z, B1.w, B2.x, B2.y, B2.z, B2.w};
            float lo[4], ha[4], hb[4];
            #pragma unroll
            for (int j = 0; j < 4; ++j) {
                float Es = 0.f, Os = 0.f, Pu = 0.f, Qu = 0.f;
                #pragma unroll
                for (int s = 0; s < 7; ++s) {
                    const float ve = we[j + 1 + s], vo = wo[j + 1 + s];
                    Es += ae[s] * ve;     Os += ao[s] * vo;
                    Pu += ao[6 - s] * ve; Qu += ae[6 - s] * vo;
                }
                lo[j] = Es + Os;
                hb[j] = Os - Es;
                ha[j] = Pu - Qu;
            }
            const int nb = N0 - 8 + ln0;
            #pragma unroll
            for (int j = 0; j < 4; ++j)
                if (nb + j < 0 || nb + j >= L2) lo[j] = 0.f;
            *(float2*)(s2e + 2 * g) = make_float2(lo[0], lo[2]);
            *(float2*)(s2o + 2 * g) = make_float2(lo[1], lo[3]);
            if (g >= 2 && g < 2 + T2 / 4) {
                const int n_out = N0 + 4 * (g - 2);
                *(float4*)(yh1 + n_out)      = make_float4(ha[0], ha[1], ha[2], ha[3]);
                *(float4*)(yh1 + L2 + n_out) = make_float4(hb[0], hb[1], hb[2], hb[3]);
            }
        }
    }
    __syncthreads();

    // ---- level 3: lo3 / hia3 / hib3 -> gmem ----
    {
        float ae[7], ao[7];
        #pragma unroll
        for (int s = 0; s < 7; ++s) { ae[s] = h0a[2 * s]; ao[s] = h0a[2 * s + 1]; }
        float* olo = out + (long)b * L3;
        float* yh2 = out + OFF_YH2 + (long)b * (2L * L3);
        for (int g = tid; g < NG3; g += 256) {
            const int lm0 = 4 * g;
            const float4 A0 = *(const float4*)(s2e + lm0);
            const float4 A1 = *(const float4*)(s2e + lm0 + 4);
            const float4 A2 = *(const float4*)(s2e + lm0 + 8);
            const float4 B0 = *(const float4*)(s2o + lm0);
            const float4 B1 = *(const float4*)(s2o + lm0 + 4);
            const float4 B2 = *(const float4*)(s2o + lm0 + 8);
            const float we[12] = {A0.x, A0.y, A0.z, A0.w, A1.x, A1.y,
                                  A1.z, A1.w, A2.x, A2.y, A2.z, A2.w};
            const float wo[12] = {B0.x, B0.y, B0.z, B0.w, B1.x, B1.y,
                                  B1.z, B1.w, B2.x, B2.y, B2.z, B2.w};
            float lo[4], ha[4], hb[4];
            #pragma unroll
            for (int j = 0; j < 4; ++j) {
                float Es = 0.f, Os = 0.f, Pu = 0.f, Qu = 0.f;
                #pragma unroll
                for (int s = 0; s < 7; ++s) {
                    const float ve = we[j + 1 + s], vo = wo[j + 1 + s];
                    Es += ae[s] * ve;     Os += ao[s] * vo;
                    Pu += ao[6 - s] * ve; Qu += ae[6 - s] * vo;
                }
                lo[j] = Es + Os;
                hb[j] = Os - Es;
                ha[j] = Pu - Qu;
            }
            const int m = M0 + lm0;
            *(float4*)(olo + m)      = make_float4(lo[0], lo[1], lo[2], lo[3]);
            *(float4*)(yh2 + m)      = make_float4(ha[0], ha[1], ha[2], ha[3]);
            *(float4*)(yh2 + L3 + m) = make_float4(hb[0], hb[1], hb[2], hb[3]);
        }
    }
}

extern "C" void kernel_launch(void* const* d_in, const int* in_sizes, int n_in,
                              void* d_out, int out_size) {
    (void)in_sizes; (void)n_in; (void)out_size;
    // metadata order: x, h0o, h1o, h0a, h1a, h0b, h1b (h1a/h0b/h1b derived algebraically)
    dim3 grid(L3 / T3, BATCH);
    dtcwt1d_fused<<<grid, 256>>>(
        (const float*)d_in[0],
        (const float*)d_in[1], (const float*)d_in[2],
        (const float*)d_in[3],
        (float*)d_out);
}